// round 5
// baseline (speedup 1.0000x reference)
#include <cuda_runtime.h>
#include <cuda_bf16.h>
#include <math.h>

#define Nn 10000
#define Ee 160000
#define HID 256
#define HEADS 8
#define Cc 32
#define Tt 5
#define EDGE_DIM 9

// ---------------- scratch (static device globals; no allocation) ----------------
__device__ float g_ea[Ee * EDGE_DIM];
__device__ float g_h[Nn * HID];
__device__ float g_xl[Nn * HID];
__device__ float g_xr[Nn * HID];
__device__ float g_out[Nn * HID];
__device__ float g_logits[Ee * HEADS];
__device__ int   g_cnt[Nn + 1];
__device__ int   g_off[Nn + 1];
__device__ int   g_cur[Nn];
__device__ int   g_elist[Ee];
__device__ double g_red[512];
__device__ float g_bnp[512];   // per-channel scale/shift
__device__ float g_eap[2 * EDGE_DIM];

// ---------------- utility zero kernels ----------------
__global__ void zero_red_k() { int i = threadIdx.x; if (i < 512) g_red[i] = 0.0; }
__global__ void zero_cnt_k() { int i = blockIdx.x * 256 + threadIdx.x; if (i <= Nn) g_cnt[i] = 0; }

// ---------------- edge-attr normalization ----------------
__global__ void ea_stats_k(const float* __restrict__ ea) {
    __shared__ double ss[EDGE_DIM], ss2[EDGE_DIM];
    if (threadIdx.x < EDGE_DIM) { ss[threadIdx.x] = 0.0; ss2[threadIdx.x] = 0.0; }
    __syncthreads();
    double ls[EDGE_DIM] = {0}, ls2[EDGE_DIM] = {0};
    for (int e = blockIdx.x * blockDim.x + threadIdx.x; e < Ee; e += gridDim.x * blockDim.x) {
        #pragma unroll
        for (int k = 0; k < EDGE_DIM; k++) {
            float x = ea[e * EDGE_DIM + k];
            ls[k] += x; ls2[k] += (double)x * x;
        }
    }
    #pragma unroll
    for (int k = 0; k < EDGE_DIM; k++) { atomicAdd(&ss[k], ls[k]); atomicAdd(&ss2[k], ls2[k]); }
    __syncthreads();
    if (threadIdx.x < EDGE_DIM) {
        atomicAdd(&g_red[threadIdx.x], ss[threadIdx.x]);
        atomicAdd(&g_red[256 + threadIdx.x], ss2[threadIdx.x]);
    }
}

// consumes g_red and resets it for the next reduction
__global__ void ea_final_k() {
    int c = threadIdx.x;
    if (c < EDGE_DIM) {
        double mu = g_red[c] / (double)Ee;
        double var = g_red[256 + c] / (double)Ee - mu * mu;
        double sd = sqrt(var > 0.0 ? var : 0.0);
        g_eap[c] = (float)mu;
        g_eap[EDGE_DIM + c] = (float)(1.0 / (sd + 1e-8));
        g_red[c] = 0.0; g_red[256 + c] = 0.0;
    }
}

__global__ void ea_norm_k(const float* __restrict__ ea) {
    int idx = blockIdx.x * 256 + threadIdx.x;
    if (idx < Ee * EDGE_DIM) {
        int c = idx % EDGE_DIM;
        g_ea[idx] = (ea[idx] - g_eap[c]) * g_eap[EDGE_DIM + c];
    }
}

// ---------------- lift: h = relu(x @ W(10x256) + b) ----------------
__global__ void lift_k(const float* __restrict__ x, const float* __restrict__ W,
                       const float* __restrict__ b) {
    int n = blockIdx.x;
    int c = threadIdx.x;
    float acc = b[c];
    #pragma unroll
    for (int k = 0; k < 10; k++) acc += x[n * 10 + k] * W[k * HID + c];
    g_h[n * HID + c] = fmaxf(acc, 0.f);
}

// ---------------- CSR build ----------------
__global__ void hist_k(const int* __restrict__ ei) {
    int e = blockIdx.x * 256 + threadIdx.x;
    if (e < Ee) atomicAdd(&g_cnt[ei[Ee + e]], 1);
}

__global__ void scan_k() {
    __shared__ int partial[1024];
    int tid = threadIdx.x;
    const int PER = 10;  // 1024*10 >= 10000
    int base = tid * PER;
    int loc[PER];
    int s = 0;
    #pragma unroll
    for (int i = 0; i < PER; i++) {
        int n = base + i;
        int v = (n < Nn) ? g_cnt[n] : 0;
        loc[i] = s; s += v;
    }
    partial[tid] = s;
    __syncthreads();
    for (int off = 1; off < 1024; off <<= 1) {
        int v = (tid >= off) ? partial[tid - off] : 0;
        __syncthreads();
        partial[tid] += v;
        __syncthreads();
    }
    int offset = (tid > 0) ? partial[tid - 1] : 0;
    #pragma unroll
    for (int i = 0; i < PER; i++) {
        int n = base + i;
        if (n < Nn) { g_off[n] = offset + loc[i]; g_cur[n] = offset + loc[i]; }
    }
    if (tid == 1023) g_off[Nn] = partial[1023];
}

__global__ void fill_k(const int* __restrict__ ei) {
    int e = blockIdx.x * 256 + threadIdx.x;
    if (e < Ee) {
        int pos = atomicAdd(&g_cur[ei[Ee + e]], 1);
        g_elist[pos] = e;
    }
}

// ---------------- fp32 SGEMM: Y[M,256] = A[M,256] @ B[256,256] + bias ----------------
// 128x128 block tile, 8x8 microtile, BK=8, double-buffered smem.
__global__ void __launch_bounds__(256, 2)
sgemm_k(const float* __restrict__ A, const float* __restrict__ B,
        const float* __restrict__ bias, float* __restrict__ Y, int M) {
    __shared__ float As[2][8][132];
    __shared__ float Bs[2][8][132];
    const int bm = blockIdx.x * 128, bn = blockIdx.y * 128;
    const int tid = threadIdx.x;
    const int arow = tid >> 1, acol = (tid & 1) * 4;
    const int brow = tid >> 5, bcol = (tid & 31) * 4;
    const int tx = tid & 15, ty = tid >> 4;
    const bool arow_ok = (bm + arow) < M;

    float acc[8][8];
    #pragma unroll
    for (int i = 0; i < 8; i++)
        #pragma unroll
        for (int j = 0; j < 8; j++) acc[i][j] = 0.f;

    // load tile 0
    {
        float4 av = make_float4(0.f, 0.f, 0.f, 0.f);
        if (arow_ok) av = *reinterpret_cast<const float4*>(&A[(bm + arow) * 256 + acol]);
        As[0][acol + 0][arow] = av.x; As[0][acol + 1][arow] = av.y;
        As[0][acol + 2][arow] = av.z; As[0][acol + 3][arow] = av.w;
        float4 bv = *reinterpret_cast<const float4*>(&B[brow * 256 + bn + bcol]);
        *reinterpret_cast<float4*>(&Bs[0][brow][bcol]) = bv;
    }
    __syncthreads();

    int buf = 0;
    #pragma unroll 1
    for (int k0 = 8; k0 <= 256; k0 += 8) {
        float4 av, bv;
        const bool has = (k0 < 256);
        if (has) {
            av = make_float4(0.f, 0.f, 0.f, 0.f);
            if (arow_ok) av = *reinterpret_cast<const float4*>(&A[(bm + arow) * 256 + k0 + acol]);
            bv = *reinterpret_cast<const float4*>(&B[(k0 + brow) * 256 + bn + bcol]);
        }
        #pragma unroll
        for (int kk = 0; kk < 8; kk++) {
            float4 a0 = *reinterpret_cast<const float4*>(&As[buf][kk][ty * 8]);
            float4 a1 = *reinterpret_cast<const float4*>(&As[buf][kk][ty * 8 + 4]);
            float4 b0 = *reinterpret_cast<const float4*>(&Bs[buf][kk][tx * 8]);
            float4 b1 = *reinterpret_cast<const float4*>(&Bs[buf][kk][tx * 8 + 4]);
            float ra[8] = {a0.x, a0.y, a0.z, a0.w, a1.x, a1.y, a1.z, a1.w};
            float rb[8] = {b0.x, b0.y, b0.z, b0.w, b1.x, b1.y, b1.z, b1.w};
            #pragma unroll
            for (int i = 0; i < 8; i++)
                #pragma unroll
                for (int j = 0; j < 8; j++) acc[i][j] = fmaf(ra[i], rb[j], acc[i][j]);
        }
        if (has) {
            const int nb = buf ^ 1;
            As[nb][acol + 0][arow] = av.x; As[nb][acol + 1][arow] = av.y;
            As[nb][acol + 2][arow] = av.z; As[nb][acol + 3][arow] = av.w;
            *reinterpret_cast<float4*>(&Bs[nb][brow][bcol]) = bv;
            __syncthreads();
            buf = nb;
        }
    }

    // epilogue with bias, vectorized
    float4 bb0 = *reinterpret_cast<const float4*>(&bias[bn + tx * 8]);
    float4 bb1 = *reinterpret_cast<const float4*>(&bias[bn + tx * 8 + 4]);
    #pragma unroll
    for (int i = 0; i < 8; i++) {
        int row = bm + ty * 8 + i;
        if (row < M) {
            float4 o0 = make_float4(acc[i][0] + bb0.x, acc[i][1] + bb0.y,
                                    acc[i][2] + bb0.z, acc[i][3] + bb0.w);
            float4 o1 = make_float4(acc[i][4] + bb1.x, acc[i][5] + bb1.y,
                                    acc[i][6] + bb1.z, acc[i][7] + bb1.w);
            *reinterpret_cast<float4*>(&Y[row * 256 + bn + tx * 8]) = o0;
            *reinterpret_cast<float4*>(&Y[row * 256 + bn + tx * 8 + 4]) = o1;
        }
    }
}

// ---------------- edge logits: warp per edge ----------------
__global__ void edge_logits_k(const int* __restrict__ ei,
                              const float* __restrict__ We, const float* __restrict__ att) {
    __shared__ float sWe[EDGE_DIM * HID];
    __shared__ float sAtt[HID];
    int tid = threadIdx.x;
    for (int i = tid; i < EDGE_DIM * HID; i += 256) sWe[i] = We[i];
    sAtt[tid] = att[tid];
    __syncthreads();
    int warp = tid >> 5, lane = tid & 31;
    int e = blockIdx.x * 8 + warp;
    if (e >= Ee) return;
    int src = ei[e], dst = ei[Ee + e];
    float a9 = (lane < EDGE_DIM) ? g_ea[e * EDGE_DIM + lane] : 0.f;
    float p[8];
    #pragma unroll
    for (int j = 0; j < 8; j++) {
        int ch = j * 32 + lane;
        float xe = 0.f;
        #pragma unroll
        for (int k = 0; k < EDGE_DIM; k++)
            xe += __shfl_sync(0xffffffffu, a9, k) * sWe[k * HID + ch];
        float v = g_xl[src * HID + ch] + g_xr[dst * HID + ch] + xe;
        v = (v > 0.f) ? v : 0.2f * v;
        p[j] = v * sAtt[j * 32 + lane];
    }
    #pragma unroll
    for (int off = 16; off; off >>= 1)
        #pragma unroll
        for (int j = 0; j < 8; j++) p[j] += __shfl_xor_sync(0xffffffffu, p[j], off);
    if (lane == 0) {
        #pragma unroll
        for (int j = 0; j < 8; j++) g_logits[e * 8 + j] = p[j];
    }
}

// ---------------- segment softmax + aggregate: warp per (node, head) ----------------
__global__ void attn_agg_k(const int* __restrict__ ei, const float* __restrict__ bias) {
    int n = blockIdx.x;
    int h = threadIdx.x >> 5, lane = threadIdx.x & 31;
    int start = g_off[n], deg = g_off[n + 1] - start;
    int oidx = n * HID + h * 32 + lane;
    if (deg == 0) { g_out[oidx] = bias[h * 32 + lane]; return; }
    float m = -INFINITY;
    for (int i = lane; i < deg; i += 32)
        m = fmaxf(m, g_logits[g_elist[start + i] * 8 + h]);
    #pragma unroll
    for (int off = 16; off; off >>= 1) m = fmaxf(m, __shfl_xor_sync(0xffffffffu, m, off));
    float ssum = 0.f;
    for (int i = lane; i < deg; i += 32)
        ssum += expf(g_logits[g_elist[start + i] * 8 + h] - m);
    #pragma unroll
    for (int off = 16; off; off >>= 1) ssum += __shfl_xor_sync(0xffffffffu, ssum, off);
    float inv = 1.f / (ssum + 1e-16f);
    float acc = 0.f;
    for (int i = 0; i < deg; i++) {
        int e = g_elist[start + i];
        float w = expf(g_logits[e * 8 + h] - m) * inv;
        acc += w * g_xl[ei[e] * HID + h * 32 + lane];
    }
    g_out[oidx] = acc + bias[h * 32 + lane];
}

// ---------------- BatchNorm ----------------
__global__ void bn_stats_k(const float* __restrict__ v) {
    int c = threadIdx.x;
    double s = 0.0, s2 = 0.0;
    for (int n = blockIdx.x; n < Nn; n += gridDim.x) {
        float x = v[n * HID + c];
        s += x; s2 += (double)x * x;
    }
    atomicAdd(&g_red[c], s);
    atomicAdd(&g_red[256 + c], s2);
}

// consumes g_red and resets it for the next reduction
__global__ void bn_final_k(const float* __restrict__ gamma, const float* __restrict__ beta) {
    int c = threadIdx.x;
    double mu = g_red[c] / (double)Nn;
    double var = g_red[256 + c] / (double)Nn - mu * mu;
    float scale = gamma[c] * rsqrtf((float)var + 1e-5f);
    g_bnp[c] = scale;
    g_bnp[256 + c] = beta[c] - (float)mu * scale;
    g_red[c] = 0.0; g_red[256 + c] = 0.0;
}

// act: 0 = elu, 1 = relu
__global__ void bn_apply_k(const float* __restrict__ v, float* __restrict__ o, int act) {
    int c = threadIdx.x;
    int idx = blockIdx.x * HID + c;
    float y = v[idx] * g_bnp[c] + g_bnp[256 + c];
    o[idx] = act ? fmaxf(y, 0.f) : ((y > 0.f) ? y : expm1f(y));
}

// ---------------- final projection: [N,256] @ [256,3] + b ----------------
__global__ void proj3_k(const float* __restrict__ W, const float* __restrict__ b,
                        float* __restrict__ out) {
    int idx = blockIdx.x * 256 + threadIdx.x;
    if (idx >= Nn * 3) return;
    int n = idx / 3, o = idx % 3;
    float acc = b[o];
    const float* hrow = &g_h[n * HID];
    #pragma unroll 8
    for (int k = 0; k < HID; k++) acc += hrow[k] * W[k * 3 + o];
    out[idx] = acc;
}

// ---------------- launch ----------------
extern "C" void kernel_launch(void* const* d_in, const int* in_sizes, int n_in,
                              void* d_out, int out_size) {
    const float* x         = (const float*)d_in[0];
    const float* edge_attr = (const float*)d_in[1];
    const int*   ei        = (const int*)  d_in[2];
    const float* lift_W    = (const float*)d_in[3];
    const float* lift_b    = (const float*)d_in[4];
    const float* Wl        = (const float*)d_in[5];
    const float* bl        = (const float*)d_in[6];
    const float* Wr        = (const float*)d_in[7];
    const float* br        = (const float*)d_in[8];
    const float* We        = (const float*)d_in[9];
    const float* att       = (const float*)d_in[10];
    const float* conv_bias = (const float*)d_in[11];
    const float* bn_gamma  = (const float*)d_in[12];
    const float* bn_beta   = (const float*)d_in[13];
    const float* p1_W      = (const float*)d_in[14];
    const float* p1_b      = (const float*)d_in[15];
    const float* pbn1_g    = (const float*)d_in[16];
    const float* pbn1_b    = (const float*)d_in[17];
    const float* p2_W      = (const float*)d_in[18];
    const float* p2_b      = (const float*)d_in[19];
    const float* pbn2_g    = (const float*)d_in[20];
    const float* pbn2_b    = (const float*)d_in[21];
    const float* p3_W      = (const float*)d_in[22];
    const float* p3_b      = (const float*)d_in[23];
    float* out = (float*)d_out;

    float* d_h   = nullptr; float* d_xl = nullptr; float* d_xr = nullptr; float* d_o = nullptr;
    cudaGetSymbolAddress((void**)&d_h,  g_h);
    cudaGetSymbolAddress((void**)&d_xl, g_xl);
    cudaGetSymbolAddress((void**)&d_xr, g_xr);
    cudaGetSymbolAddress((void**)&d_o,  g_out);

    dim3 ggrid((Nn + 127) / 128, 2);

    // edge-attr normalization (g_red starts zeroed; each *_final_k re-zeros it)
    zero_red_k<<<1, 512>>>();
    ea_stats_k<<<64, 256>>>(edge_attr);
    ea_final_k<<<1, 32>>>();
    ea_norm_k<<<(Ee * EDGE_DIM + 255) / 256, 256>>>(edge_attr);

    // lift
    lift_k<<<Nn, HID>>>(x, lift_W, lift_b);

    // CSR by destination
    zero_cnt_k<<<(Nn + 256) / 256, 256>>>();
    hist_k<<<Ee / 256, 256>>>(ei);
    scan_k<<<1, 1024>>>();
    fill_k<<<Ee / 256, 256>>>(ei);

    for (int t = 0; t < Tt; t++) {
        sgemm_k<<<ggrid, 256>>>(d_h, Wl + t * HID * HID, bl + t * HID, d_xl, Nn);
        sgemm_k<<<ggrid, 256>>>(d_h, Wr + t * HID * HID, br + t * HID, d_xr, Nn);
        edge_logits_k<<<Ee / 8, 256>>>(ei, We + t * EDGE_DIM * HID, att + t * HEADS * Cc);
        attn_agg_k<<<Nn, 256>>>(ei, conv_bias + t * HID);
        bn_stats_k<<<80, 256>>>(d_o);
        bn_final_k<<<1, 256>>>(bn_gamma + t * HID, bn_beta + t * HID);
        bn_apply_k<<<Nn, HID>>>(d_o, d_h, 0);
    }

    // projection MLP
    sgemm_k<<<ggrid, 256>>>(d_h, p1_W, p1_b, d_o, Nn);
    bn_stats_k<<<80, 256>>>(d_o);
    bn_final_k<<<1, 256>>>(pbn1_g, pbn1_b);
    bn_apply_k<<<Nn, HID>>>(d_o, d_h, 1);

    sgemm_k<<<ggrid, 256>>>(d_h, p2_W, p2_b, d_o, Nn);
    bn_stats_k<<<80, 256>>>(d_o);
    bn_final_k<<<1, 256>>>(pbn2_g, pbn2_b);
    bn_apply_k<<<Nn, HID>>>(d_o, d_h, 1);

    proj3_k<<<(Nn * 3 + 255) / 256, 256>>>(p3_W, p3_b, out);
}

// round 7
// speedup vs baseline: 1.2479x; 1.2479x over previous
#include <cuda_runtime.h>
#include <cuda_bf16.h>
#include <math.h>
#include <stdint.h>

#define Nn 10000
#define Ee 160000
#define HID 256
#define HEADS 8
#define Cc 32
#define Tt 5
#define EDGE_DIM 9

// ---------------- scratch (static device globals; no allocation) ----------------
__device__ float g_ea[Ee * EDGE_DIM];
__device__ float g_h[Nn * HID];
__device__ float g_xl[Nn * HID];
__device__ float g_xr[Nn * HID];
__device__ float g_out[Nn * HID];
__device__ float g_logits[Ee * HEADS];
__device__ int   g_cnt[Nn + 1];
__device__ int   g_off[Nn + 1];
__device__ int   g_cur[Nn];
__device__ int   g_elist[Ee];
__device__ double g_red[512];
__device__ float g_bnp[512];
__device__ float g_eap[2 * EDGE_DIM];

// ---------------- utility ----------------
__global__ void zero_red_k() { int i = threadIdx.x; if (i < 512) g_red[i] = 0.0; }
__global__ void zero_cnt_k() { int i = blockIdx.x * 256 + threadIdx.x; if (i <= Nn) g_cnt[i] = 0; }

// ---------------- edge-attr normalization ----------------
__global__ void ea_stats_k(const float* __restrict__ ea) {
    __shared__ double ss[EDGE_DIM], ss2[EDGE_DIM];
    if (threadIdx.x < EDGE_DIM) { ss[threadIdx.x] = 0.0; ss2[threadIdx.x] = 0.0; }
    __syncthreads();
    double ls[EDGE_DIM] = {0}, ls2[EDGE_DIM] = {0};
    for (int e = blockIdx.x * blockDim.x + threadIdx.x; e < Ee; e += gridDim.x * blockDim.x) {
        #pragma unroll
        for (int k = 0; k < EDGE_DIM; k++) {
            float x = ea[e * EDGE_DIM + k];
            ls[k] += x; ls2[k] += (double)x * x;
        }
    }
    #pragma unroll
    for (int k = 0; k < EDGE_DIM; k++) { atomicAdd(&ss[k], ls[k]); atomicAdd(&ss2[k], ls2[k]); }
    __syncthreads();
    if (threadIdx.x < EDGE_DIM) {
        atomicAdd(&g_red[threadIdx.x], ss[threadIdx.x]);
        atomicAdd(&g_red[256 + threadIdx.x], ss2[threadIdx.x]);
    }
}

__global__ void ea_final_k() {
    int c = threadIdx.x;
    if (c < EDGE_DIM) {
        double mu = g_red[c] / (double)Ee;
        double var = g_red[256 + c] / (double)Ee - mu * mu;
        double sd = sqrt(var > 0.0 ? var : 0.0);
        g_eap[c] = (float)mu;
        g_eap[EDGE_DIM + c] = (float)(1.0 / (sd + 1e-8));
        g_red[c] = 0.0; g_red[256 + c] = 0.0;
    }
}

__global__ void ea_norm_k(const float* __restrict__ ea) {
    int idx = blockIdx.x * 256 + threadIdx.x;
    if (idx < Ee * EDGE_DIM) {
        int c = idx % EDGE_DIM;
        g_ea[idx] = (ea[idx] - g_eap[c]) * g_eap[EDGE_DIM + c];
    }
}

// ---------------- lift ----------------
__global__ void lift_k(const float* __restrict__ x, const float* __restrict__ W,
                       const float* __restrict__ b) {
    int n = blockIdx.x;
    int c = threadIdx.x;
    float acc = b[c];
    #pragma unroll
    for (int k = 0; k < 10; k++) acc += x[n * 10 + k] * W[k * HID + c];
    g_h[n * HID + c] = fmaxf(acc, 0.f);
}

// ---------------- CSR build ----------------
__global__ void hist_k(const int* __restrict__ ei) {
    int e = blockIdx.x * 256 + threadIdx.x;
    if (e < Ee) atomicAdd(&g_cnt[ei[Ee + e]], 1);
}

__global__ void scan_k() {
    __shared__ int partial[1024];
    int tid = threadIdx.x;
    const int PER = 10;
    int base = tid * PER;
    int loc[PER];
    int s = 0;
    #pragma unroll
    for (int i = 0; i < PER; i++) {
        int n = base + i;
        int v = (n < Nn) ? g_cnt[n] : 0;
        loc[i] = s; s += v;
    }
    partial[tid] = s;
    __syncthreads();
    for (int off = 1; off < 1024; off <<= 1) {
        int v = (tid >= off) ? partial[tid - off] : 0;
        __syncthreads();
        partial[tid] += v;
        __syncthreads();
    }
    int offset = (tid > 0) ? partial[tid - 1] : 0;
    #pragma unroll
    for (int i = 0; i < PER; i++) {
        int n = base + i;
        if (n < Nn) { g_off[n] = offset + loc[i]; g_cur[n] = offset + loc[i]; }
    }
    if (tid == 1023) g_off[Nn] = partial[1023];
}

__global__ void fill_k(const int* __restrict__ ei) {
    int e = blockIdx.x * 256 + threadIdx.x;
    if (e < Ee) {
        int pos = atomicAdd(&g_cur[ei[Ee + e]], 1);
        g_elist[pos] = e;
    }
}

// ================= bf16-split HMMA GEMM (mma.sync, baseline PTX) =================
// Y[M,256] = A[M,256]@W[256,256] + bias via Ah@Wh + Ah@Wl + Al@Wh, fp32 accum.
// CTA: 128(M) x 128(N), 8 warps (4Mx2N), warp 32x64, m16n8k16 tiles.
// smem: A tiles padded to 40 bf16/row (80B), B tiles padded to 136 bf16/row (272B)
// -> conflict-free ldmatrix (distinct 4-bank groups per 8 rows).

#define ASH_OFF 0
#define ASL_OFF 10240
#define BSH_OFF 20480
#define BSL_OFF 29184
#define GSM_TOT 37888

__device__ __forceinline__ uint32_t smem_u32(const void* p) {
    uint32_t a;
    asm("{ .reg .u64 t; cvta.to.shared.u64 t, %1; cvt.u32.u64 %0, t; }" : "=r"(a) : "l"(p));
    return a;
}
__device__ __forceinline__ void ldsm_x4(uint32_t* r, uint32_t addr) {
    asm volatile("ldmatrix.sync.aligned.m8n8.x4.shared.b16 {%0,%1,%2,%3}, [%4];"
                 : "=r"(r[0]), "=r"(r[1]), "=r"(r[2]), "=r"(r[3]) : "r"(addr));
}
__device__ __forceinline__ void ldsm_x4_t(uint32_t* r, uint32_t addr) {
    asm volatile("ldmatrix.sync.aligned.m8n8.x4.trans.shared.b16 {%0,%1,%2,%3}, [%4];"
                 : "=r"(r[0]), "=r"(r[1]), "=r"(r[2]), "=r"(r[3]) : "r"(addr));
}
__device__ __forceinline__ void mma_bf16(float& d0, float& d1, float& d2, float& d3,
                                         const uint32_t* a, uint32_t b0, uint32_t b1) {
    asm volatile(
        "mma.sync.aligned.m16n8k16.row.col.f32.bf16.bf16.f32 "
        "{%0,%1,%2,%3}, {%4,%5,%6,%7}, {%8,%9}, {%0,%1,%2,%3};"
        : "+f"(d0), "+f"(d1), "+f"(d2), "+f"(d3)
        : "r"(a[0]), "r"(a[1]), "r"(a[2]), "r"(a[3]), "r"(b0), "r"(b1));
}
__device__ __forceinline__ void split2(float x, float y, uint32_t& hi, uint32_t& lo) {
    __nv_bfloat162 h = __floats2bfloat162_rn(x, y);
    float rx = x - __bfloat162float(h.x);
    float ry = y - __bfloat162float(h.y);
    __nv_bfloat162 l = __floats2bfloat162_rn(rx, ry);
    hi = *reinterpret_cast<uint32_t*>(&h);
    lo = *reinterpret_cast<uint32_t*>(&l);
}

__global__ void __launch_bounds__(256)
hgemm_k(const float* __restrict__ A,
        const float* __restrict__ W0, const float* __restrict__ b0, float* __restrict__ Y0,
        const float* __restrict__ W1, const float* __restrict__ b1, float* __restrict__ Y1,
        int M) {
    __shared__ __align__(16) char sm[GSM_TOT];
    const uint32_t sb = smem_u32(sm);
    const int tid = threadIdx.x;
    const int wid = tid >> 5, lane = tid & 31;
    const int bm = blockIdx.x * 128, bn = blockIdx.y * 128;
    const float* W    = blockIdx.z ? W1 : W0;
    const float* bias = blockIdx.z ? b1 : b0;
    float*       Y    = blockIdx.z ? Y1 : Y0;

    const int warp_m = (wid >> 1) * 32;
    const int warp_n = (wid & 1) * 64;

    // A conversion mapping: row = tid>>1, k-half = (tid&1)*16
    const int ar = tid >> 1, akseg = (tid & 1) * 16;
    const bool ar_ok = (bm + ar) < M;
    const float* aptr = A + (size_t)(bm + ar) * 256 + akseg;
    // B conversion mapping: k-row = tid>>3, n-seg = (tid&7)*16
    const int br_ = tid >> 3, bcseg = (tid & 7) * 16;
    const float* bptr = W + (size_t)br_ * 256 + bn + bcseg;

    float acc[2][8][4];
    #pragma unroll
    for (int i = 0; i < 2; i++)
        #pragma unroll
        for (int j = 0; j < 8; j++)
            #pragma unroll
            for (int k = 0; k < 4; k++) acc[i][j][k] = 0.f;

    // ldmatrix source addresses (per lane)
    // A tile (16x16): row = lane&15, 16B-half = lane>>4
    const uint32_t aAddrBaseH = sb + ASH_OFF + (uint32_t)(warp_m + (lane & 15)) * 80 + (lane >> 4) * 16;
    const uint32_t aAddrBaseL = aAddrBaseH + (ASL_OFF - ASH_OFF);
    // B tile (k16 x n16): g=lane>>3: k = (g&1)*8 + (lane&7), n-off = (g>>1)*8
    const int bg = lane >> 3;
    const uint32_t bAddrBaseH = sb + BSH_OFF + (uint32_t)((bg & 1) * 8 + (lane & 7)) * 272
                              + (uint32_t)(warp_n + (bg >> 1) * 8) * 2;
    const uint32_t bAddrBaseL = bAddrBaseH + (BSL_OFF - BSH_OFF);

    #pragma unroll 1
    for (int kc = 0; kc < 8; kc++) {
        const int k0 = kc * 32;
        if (kc > 0) __syncthreads();
        // ---- convert A chunk: 128 rows x 32 k ----
        {
            char* dsth = sm + ASH_OFF + ar * 80 + akseg * 2;
            char* dstl = sm + ASL_OFF + ar * 80 + akseg * 2;
            #pragma unroll
            for (int i = 0; i < 4; i++) {
                float4 v = ar_ok ? *reinterpret_cast<const float4*>(aptr + k0 + i * 4)
                                 : make_float4(0.f, 0.f, 0.f, 0.f);
                uint2 uh, ul;
                split2(v.x, v.y, uh.x, ul.x);
                split2(v.z, v.w, uh.y, ul.y);
                *reinterpret_cast<uint2*>(dsth + i * 8) = uh;
                *reinterpret_cast<uint2*>(dstl + i * 8) = ul;
            }
        }
        // ---- convert B chunk: 32 k-rows x 128 n ----
        {
            char* dsth = sm + BSH_OFF + br_ * 272 + bcseg * 2;
            char* dstl = sm + BSL_OFF + br_ * 272 + bcseg * 2;
            const float* bp = bptr + (size_t)k0 * 256;
            #pragma unroll
            for (int i = 0; i < 4; i++) {
                float4 v = *reinterpret_cast<const float4*>(bp + i * 4);
                uint2 uh, ul;
                split2(v.x, v.y, uh.x, ul.x);
                split2(v.z, v.w, uh.y, ul.y);
                *reinterpret_cast<uint2*>(dsth + i * 8) = uh;
                *reinterpret_cast<uint2*>(dstl + i * 8) = ul;
            }
        }
        __syncthreads();

        #pragma unroll
        for (int ks = 0; ks < 2; ks++) {
            uint32_t bh[4][4], bl[4][4];
            #pragma unroll
            for (int nt = 0; nt < 4; nt++) {
                uint32_t off = (uint32_t)(ks * 16) * 272 + (uint32_t)(nt * 16) * 2;
                ldsm_x4_t(bh[nt], bAddrBaseH + off);
                ldsm_x4_t(bl[nt], bAddrBaseL + off);
            }
            #pragma unroll
            for (int mt = 0; mt < 2; mt++) {
                uint32_t ah[4], al[4];
                uint32_t aoff = (uint32_t)(mt * 16) * 80 + (uint32_t)(ks * 32);
                ldsm_x4(ah, aAddrBaseH + aoff);
                ldsm_x4(al, aAddrBaseL + aoff);
                #pragma unroll
                for (int nt = 0; nt < 4; nt++) {
                    float* d0 = acc[mt][nt * 2];
                    float* d1 = acc[mt][nt * 2 + 1];
                    mma_bf16(d0[0], d0[1], d0[2], d0[3], ah, bh[nt][0], bh[nt][1]);
                    mma_bf16(d1[0], d1[1], d1[2], d1[3], ah, bh[nt][2], bh[nt][3]);
                    mma_bf16(d0[0], d0[1], d0[2], d0[3], ah, bl[nt][0], bl[nt][1]);
                    mma_bf16(d1[0], d1[1], d1[2], d1[3], ah, bl[nt][2], bl[nt][3]);
                    mma_bf16(d0[0], d0[1], d0[2], d0[3], al, bh[nt][0], bh[nt][1]);
                    mma_bf16(d1[0], d1[1], d1[2], d1[3], al, bh[nt][2], bh[nt][3]);
                }
            }
        }
    }

    // ---- epilogue: d-frag rows = lane>>2 (+8), cols = (lane&3)*2 ----
    const int crow = lane >> 2, ccol = (lane & 3) * 2;
    #pragma unroll
    for (int mt = 0; mt < 2; mt++) {
        int row0 = bm + warp_m + mt * 16 + crow;
        #pragma unroll
        for (int nt8 = 0; nt8 < 8; nt8++) {
            int col = bn + warp_n + nt8 * 8 + ccol;
            float bx = bias[col], by = bias[col + 1];
            if (row0 < M) {
                float2 o = make_float2(acc[mt][nt8][0] + bx, acc[mt][nt8][1] + by);
                *reinterpret_cast<float2*>(Y + (size_t)row0 * 256 + col) = o;
            }
            if (row0 + 8 < M) {
                float2 o = make_float2(acc[mt][nt8][2] + bx, acc[mt][nt8][3] + by);
                *reinterpret_cast<float2*>(Y + (size_t)(row0 + 8) * 256 + col) = o;
            }
        }
    }
}

// ---------------- edge logits: warp per edge ----------------
__global__ void edge_logits_k(const int* __restrict__ ei,
                              const float* __restrict__ We, const float* __restrict__ att) {
    __shared__ float sWe[EDGE_DIM * HID];
    __shared__ float sAtt[HID];
    int tid = threadIdx.x;
    for (int i = tid; i < EDGE_DIM * HID; i += 256) sWe[i] = We[i];
    sAtt[tid] = att[tid];
    __syncthreads();
    int warp = tid >> 5, lane = tid & 31;
    int e = blockIdx.x * 8 + warp;
    if (e >= Ee) return;
    int src = ei[e], dst = ei[Ee + e];
    float a9 = (lane < EDGE_DIM) ? g_ea[e * EDGE_DIM + lane] : 0.f;
    float p[8];
    #pragma unroll
    for (int j = 0; j < 8; j++) {
        int ch = j * 32 + lane;
        float xe = 0.f;
        #pragma unroll
        for (int k = 0; k < EDGE_DIM; k++)
            xe += __shfl_sync(0xffffffffu, a9, k) * sWe[k * HID + ch];
        float v = g_xl[src * HID + ch] + g_xr[dst * HID + ch] + xe;
        v = (v > 0.f) ? v : 0.2f * v;
        p[j] = v * sAtt[j * 32 + lane];
    }
    #pragma unroll
    for (int off = 16; off; off >>= 1)
        #pragma unroll
        for (int j = 0; j < 8; j++) p[j] += __shfl_xor_sync(0xffffffffu, p[j], off);
    if (lane == 0) {
        #pragma unroll
        for (int j = 0; j < 8; j++) g_logits[e * 8 + j] = p[j];
    }
}

// ---------------- segment softmax + aggregate ----------------
__global__ void attn_agg_k(const int* __restrict__ ei, const float* __restrict__ bias) {
    int n = blockIdx.x;
    int h = threadIdx.x >> 5, lane = threadIdx.x & 31;
    int start = g_off[n], deg = g_off[n + 1] - start;
    int oidx = n * HID + h * 32 + lane;
    if (deg == 0) { g_out[oidx] = bias[h * 32 + lane]; return; }
    float m = -INFINITY;
    for (int i = lane; i < deg; i += 32)
        m = fmaxf(m, g_logits[g_elist[start + i] * 8 + h]);
    #pragma unroll
    for (int off = 16; off; off >>= 1) m = fmaxf(m, __shfl_xor_sync(0xffffffffu, m, off));
    float ssum = 0.f;
    for (int i = lane; i < deg; i += 32)
        ssum += expf(g_logits[g_elist[start + i] * 8 + h] - m);
    #pragma unroll
    for (int off = 16; off; off >>= 1) ssum += __shfl_xor_sync(0xffffffffu, ssum, off);
    float inv = 1.f / (ssum + 1e-16f);
    float acc = 0.f;
    for (int i = 0; i < deg; i++) {
        int e = g_elist[start + i];
        float w = expf(g_logits[e * 8 + h] - m) * inv;
        acc += w * g_xl[ei[e] * HID + h * 32 + lane];
    }
    g_out[oidx] = acc + bias[h * 32 + lane];
}

// ---------------- BatchNorm ----------------
__global__ void bn_stats_k(const float* __restrict__ v) {
    int c = threadIdx.x;
    double s = 0.0, s2 = 0.0;
    for (int n = blockIdx.x; n < Nn; n += gridDim.x) {
        float x = v[n * HID + c];
        s += x; s2 += (double)x * x;
    }
    atomicAdd(&g_red[c], s);
    atomicAdd(&g_red[256 + c], s2);
}

__global__ void bn_final_k(const float* __restrict__ gamma, const float* __restrict__ beta) {
    int c = threadIdx.x;
    double mu = g_red[c] / (double)Nn;
    double var = g_red[256 + c] / (double)Nn - mu * mu;
    float scale = gamma[c] * rsqrtf((float)var + 1e-5f);
    g_bnp[c] = scale;
    g_bnp[256 + c] = beta[c] - (float)mu * scale;
    g_red[c] = 0.0; g_red[256 + c] = 0.0;
}

__global__ void bn_apply_k(const float* __restrict__ v, float* __restrict__ o, int act) {
    int c = threadIdx.x;
    int idx = blockIdx.x * HID + c;
    float y = v[idx] * g_bnp[c] + g_bnp[256 + c];
    o[idx] = act ? fmaxf(y, 0.f) : ((y > 0.f) ? y : expm1f(y));
}

// ---------------- final projection ----------------
__global__ void proj3_k(const float* __restrict__ W, const float* __restrict__ b,
                        float* __restrict__ out) {
    int idx = blockIdx.x * 256 + threadIdx.x;
    if (idx >= Nn * 3) return;
    int n = idx / 3, o = idx % 3;
    float acc = b[o];
    const float* hrow = &g_h[n * HID];
    #pragma unroll 8
    for (int k = 0; k < HID; k++) acc += hrow[k] * W[k * 3 + o];
    out[idx] = acc;
}

// ---------------- launch ----------------
extern "C" void kernel_launch(void* const* d_in, const int* in_sizes, int n_in,
                              void* d_out, int out_size) {
    const float* x         = (const float*)d_in[0];
    const float* edge_attr = (const float*)d_in[1];
    const int*   ei        = (const int*)  d_in[2];
    const float* lift_W    = (const float*)d_in[3];
    const float* lift_b    = (const float*)d_in[4];
    const float* Wl        = (const float*)d_in[5];
    const float* bl        = (const float*)d_in[6];
    const float* Wr        = (const float*)d_in[7];
    const float* br        = (const float*)d_in[8];
    const float* We        = (const float*)d_in[9];
    const float* att       = (const float*)d_in[10];
    const float* conv_bias = (const float*)d_in[11];
    const float* bn_gamma  = (const float*)d_in[12];
    const float* bn_beta   = (const float*)d_in[13];
    const float* p1_W      = (const float*)d_in[14];
    const float* p1_b      = (const float*)d_in[15];
    const float* pbn1_g    = (const float*)d_in[16];
    const float* pbn1_b    = (const float*)d_in[17];
    const float* p2_W      = (const float*)d_in[18];
    const float* p2_b      = (const float*)d_in[19];
    const float* pbn2_g    = (const float*)d_in[20];
    const float* pbn2_b    = (const float*)d_in[21];
    const float* p3_W      = (const float*)d_in[22];
    const float* p3_b      = (const float*)d_in[23];
    float* out = (float*)d_out;

    float* d_h = nullptr; float* d_xl = nullptr; float* d_xr = nullptr; float* d_o = nullptr;
    cudaGetSymbolAddress((void**)&d_h,  g_h);
    cudaGetSymbolAddress((void**)&d_xl, g_xl);
    cudaGetSymbolAddress((void**)&d_xr, g_xr);
    cudaGetSymbolAddress((void**)&d_o,  g_out);

    const dim3 grid2((Nn + 127) / 128, 2, 2);  // dual gemm (Wl, Wr)
    const dim3 grid1((Nn + 127) / 128, 2, 1);  // single gemm

    // edge-attr normalization
    zero_red_k<<<1, 512>>>();
    ea_stats_k<<<64, 256>>>(edge_attr);
    ea_final_k<<<1, 32>>>();
    ea_norm_k<<<(Ee * EDGE_DIM + 255) / 256, 256>>>(edge_attr);

    // lift
    lift_k<<<Nn, HID>>>(x, lift_W, lift_b);

    // CSR by destination
    zero_cnt_k<<<(Nn + 256) / 256, 256>>>();
    hist_k<<<Ee / 256, 256>>>(ei);
    scan_k<<<1, 1024>>>();
    fill_k<<<Ee / 256, 256>>>(ei);

    for (int t = 0; t < Tt; t++) {
        hgemm_k<<<grid2, 256>>>(d_h,
            Wl + t * HID * HID, bl + t * HID, d_xl,
            Wr + t * HID * HID, br + t * HID, d_xr, Nn);
        edge_logits_k<<<Ee / 8, 256>>>(ei, We + t * EDGE_DIM * HID, att + t * HEADS * Cc);
        attn_agg_k<<<Nn, 256>>>(ei, conv_bias + t * HID);
        bn_stats_k<<<80, 256>>>(d_o);
        bn_final_k<<<1, 256>>>(bn_gamma + t * HID, bn_beta + t * HID);
        bn_apply_k<<<Nn, HID>>>(d_o, d_h, 0);
    }

    // projection MLP
    hgemm_k<<<grid1, 256>>>(d_h, p1_W, p1_b, d_o, p1_W, p1_b, d_o, Nn);
    bn_stats_k<<<80, 256>>>(d_o);
    bn_final_k<<<1, 256>>>(pbn1_g, pbn1_b);
    bn_apply_k<<<Nn, HID>>>(d_o, d_h, 1);

    hgemm_k<<<grid1, 256>>>(d_h, p2_W, p2_b, d_o, p2_W, p2_b, d_o, Nn);
    bn_stats_k<<<80, 256>>>(d_o);
    bn_final_k<<<1, 256>>>(pbn2_g, pbn2_b);
    bn_apply_k<<<Nn, HID>>>(d_o, d_h, 1);

    proj3_k<<<(Nn * 3 + 255) / 256, 256>>>(p3_W, p3_b, out);
}

// round 10
// speedup vs baseline: 1.2910x; 1.0346x over previous
#include <cuda_runtime.h>
#include <cuda_bf16.h>
#include <math.h>
#include <stdint.h>

#define Nn 10000
#define Ee 160000
#define HID 256
#define HEADS 8
#define Cc 32
#define Tt 5
#define EDGE_DIM 9

// ---------------- scratch (static device globals; no allocation) ----------------
__device__ float g_ea[Ee * EDGE_DIM];
__device__ float g_h[Nn * HID];
__device__ float g_xl[Nn * HID];
__device__ float g_xr[Nn * HID];
__device__ float g_out[Nn * HID];
__device__ float g_logits[Ee * HEADS];
__device__ int   g_cnt[Nn + 1];
__device__ int   g_off[Nn + 1];
__device__ int   g_cur[Nn];
__device__ int   g_elist[Ee];
__device__ double g_red[512];
__device__ float g_bnp[512];
__device__ float g_eap[2 * EDGE_DIM];
// bf16 hi/lo copies for tensor-core GEMM
__device__ __nv_bfloat16 g_hh[Nn * HID];
__device__ __nv_bfloat16 g_hl[Nn * HID];
__device__ __nv_bfloat16 g_Wbh[12 * HID * HID];
__device__ __nv_bfloat16 g_Wbl[12 * HID * HID];

// ---------------- utility ----------------
__global__ void zero_red_k() { int i = threadIdx.x; if (i < 512) g_red[i] = 0.0; }
__global__ void zero_cnt_k() { int i = blockIdx.x * 256 + threadIdx.x; if (i <= Nn) g_cnt[i] = 0; }

__device__ __forceinline__ void split1(float x, __nv_bfloat16& hi, __nv_bfloat16& lo) {
    hi = __float2bfloat16_rn(x);
    lo = __float2bfloat16_rn(x - __bfloat162float(hi));
}

// ---------------- weight pre-conversion: 12 slots of 256x256 ----------------
// slots 0-4: Wl[t], 5-9: Wr[t], 10: p1_W, 11: p2_W
__global__ void wconv_k(const float* __restrict__ Wl, const float* __restrict__ Wr,
                        const float* __restrict__ p1, const float* __restrict__ p2) {
    int idx = blockIdx.x * 256 + threadIdx.x;  // 12*65536 total
    int slot = idx >> 16, e = idx & 65535;
    float v;
    if (slot < 5)       v = Wl[slot * 65536 + e];
    else if (slot < 10) v = Wr[(slot - 5) * 65536 + e];
    else if (slot == 10) v = p1[e];
    else                 v = p2[e];
    __nv_bfloat16 hi, lo;
    split1(v, hi, lo);
    g_Wbh[idx] = hi; g_Wbl[idx] = lo;
}

// ---------------- edge-attr normalization ----------------
__global__ void ea_stats_k(const float* __restrict__ ea) {
    __shared__ double ss[EDGE_DIM], ss2[EDGE_DIM];
    if (threadIdx.x < EDGE_DIM) { ss[threadIdx.x] = 0.0; ss2[threadIdx.x] = 0.0; }
    __syncthreads();
    double ls[EDGE_DIM] = {0}, ls2[EDGE_DIM] = {0};
    for (int e = blockIdx.x * blockDim.x + threadIdx.x; e < Ee; e += gridDim.x * blockDim.x) {
        #pragma unroll
        for (int k = 0; k < EDGE_DIM; k++) {
            float x = ea[e * EDGE_DIM + k];
            ls[k] += x; ls2[k] += (double)x * x;
        }
    }
    #pragma unroll
    for (int k = 0; k < EDGE_DIM; k++) { atomicAdd(&ss[k], ls[k]); atomicAdd(&ss2[k], ls2[k]); }
    __syncthreads();
    if (threadIdx.x < EDGE_DIM) {
        atomicAdd(&g_red[threadIdx.x], ss[threadIdx.x]);
        atomicAdd(&g_red[256 + threadIdx.x], ss2[threadIdx.x]);
    }
}

__global__ void ea_final_k() {
    int c = threadIdx.x;
    if (c < EDGE_DIM) {
        double mu = g_red[c] / (double)Ee;
        double var = g_red[256 + c] / (double)Ee - mu * mu;
        double sd = sqrt(var > 0.0 ? var : 0.0);
        g_eap[c] = (float)mu;
        g_eap[EDGE_DIM + c] = (float)(1.0 / (sd + 1e-8));
        g_red[c] = 0.0; g_red[256 + c] = 0.0;
    }
}

__global__ void ea_norm_k(const float* __restrict__ ea) {
    int idx = blockIdx.x * 256 + threadIdx.x;
    if (idx < Ee * EDGE_DIM) {
        int c = idx % EDGE_DIM;
        g_ea[idx] = (ea[idx] - g_eap[c]) * g_eap[EDGE_DIM + c];
    }
}

// ---------------- lift ----------------
__global__ void lift_k(const float* __restrict__ x, const float* __restrict__ W,
                       const float* __restrict__ b) {
    int n = blockIdx.x;
    int c = threadIdx.x;
    float acc = b[c];
    #pragma unroll
    for (int k = 0; k < 10; k++) acc += x[n * 10 + k] * W[k * HID + c];
    float h = fmaxf(acc, 0.f);
    g_h[n * HID + c] = h;
    __nv_bfloat16 hi, lo;
    split1(h, hi, lo);
    g_hh[n * HID + c] = hi; g_hl[n * HID + c] = lo;
}

// ---------------- CSR build ----------------
__global__ void hist_k(const int* __restrict__ ei) {
    int e = blockIdx.x * 256 + threadIdx.x;
    if (e < Ee) atomicAdd(&g_cnt[ei[Ee + e]], 1);
}

__global__ void scan_k() {
    __shared__ int partial[1024];
    int tid = threadIdx.x;
    const int PER = 10;
    int base = tid * PER;
    int loc[PER];
    int s = 0;
    #pragma unroll
    for (int i = 0; i < PER; i++) {
        int n = base + i;
        int v = (n < Nn) ? g_cnt[n] : 0;
        loc[i] = s; s += v;
    }
    partial[tid] = s;
    __syncthreads();
    for (int off = 1; off < 1024; off <<= 1) {
        int v = (tid >= off) ? partial[tid - off] : 0;
        __syncthreads();
        partial[tid] += v;
        __syncthreads();
    }
    int offset = (tid > 0) ? partial[tid - 1] : 0;
    #pragma unroll
    for (int i = 0; i < PER; i++) {
        int n = base + i;
        if (n < Nn) { g_off[n] = offset + loc[i]; g_cur[n] = offset + loc[i]; }
    }
    if (tid == 1023) g_off[Nn] = partial[1023];
}

__global__ void fill_k(const int* __restrict__ ei) {
    int e = blockIdx.x * 256 + threadIdx.x;
    if (e < Ee) {
        int pos = atomicAdd(&g_cur[ei[Ee + e]], 1);
        g_elist[pos] = e;
    }
}

// ================= bf16-split HMMA GEMM (preconverted inputs) =================
// Y[M,256] = A@W + bias via Ah@Wh + Ah@Wl + Al@Wh, fp32 accum.
// CTA: 128x128, 8 warps (4Mx2N), warp 32x64, m16n8k16. A/B preconverted bf16 hi/lo.
// smem: A rows padded to 80B, B rows padded to 272B (conflict-free ldmatrix).
// Register prefetch of next K-chunk overlaps global latency with mma.

#define ASH_OFF 0
#define ASL_OFF 10240
#define BSH_OFF 20480
#define BSL_OFF 29184
#define GSM_TOT 37888

__device__ __forceinline__ uint32_t smem_u32(const void* p) {
    uint32_t a;
    asm("{ .reg .u64 t; cvta.to.shared.u64 t, %1; cvt.u32.u64 %0, t; }" : "=r"(a) : "l"(p));
    return a;
}
__device__ __forceinline__ void ldsm_x4(uint32_t* r, uint32_t addr) {
    asm volatile("ldmatrix.sync.aligned.m8n8.x4.shared.b16 {%0,%1,%2,%3}, [%4];"
                 : "=r"(r[0]), "=r"(r[1]), "=r"(r[2]), "=r"(r[3]) : "r"(addr));
}
__device__ __forceinline__ void ldsm_x4_t(uint32_t* r, uint32_t addr) {
    asm volatile("ldmatrix.sync.aligned.m8n8.x4.trans.shared.b16 {%0,%1,%2,%3}, [%4];"
                 : "=r"(r[0]), "=r"(r[1]), "=r"(r[2]), "=r"(r[3]) : "r"(addr));
}
__device__ __forceinline__ void mma_bf16(float& d0, float& d1, float& d2, float& d3,
                                         const uint32_t* a, uint32_t b0, uint32_t b1) {
    asm volatile(
        "mma.sync.aligned.m16n8k16.row.col.f32.bf16.bf16.f32 "
        "{%0,%1,%2,%3}, {%4,%5,%6,%7}, {%8,%9}, {%0,%1,%2,%3};"
        : "+f"(d0), "+f"(d1), "+f"(d2), "+f"(d3)
        : "r"(a[0]), "r"(a[1]), "r"(a[2]), "r"(a[3]), "r"(b0), "r"(b1));
}

__global__ void __launch_bounds__(256)
hgemm_k(const __nv_bfloat16* __restrict__ Bh0, const __nv_bfloat16* __restrict__ Bl0,
        const float* __restrict__ b0, float* __restrict__ Y0,
        const __nv_bfloat16* __restrict__ Bh1, const __nv_bfloat16* __restrict__ Bl1,
        const float* __restrict__ b1, float* __restrict__ Y1,
        int M) {
    __shared__ __align__(16) char sm[GSM_TOT];
    const uint32_t sb = smem_u32(sm);
    const int tid = threadIdx.x;
    const int wid = tid >> 5, lane = tid & 31;
    const int bm = blockIdx.x * 128, bn = blockIdx.y * 128;
    const __nv_bfloat16* Bh  = blockIdx.z ? Bh1 : Bh0;
    const __nv_bfloat16* Bl  = blockIdx.z ? Bl1 : Bl0;
    const float* bias        = blockIdx.z ? b1 : b0;
    float*       Y           = blockIdx.z ? Y1 : Y0;

    const int warp_m = (wid >> 1) * 32;
    const int warp_n = (wid & 1) * 64;

    // A fill mapping: row = tid>>1, k-seg = (tid&1)*16 elems (32B = 2 uint4)
    const int ar = tid >> 1, akseg = (tid & 1) * 16;
    const bool ar_ok = (bm + ar) < M;
    const __nv_bfloat16* gAh = g_hh + (size_t)(bm + ar) * 256 + akseg;
    const __nv_bfloat16* gAl = g_hl + (size_t)(bm + ar) * 256 + akseg;
    // B fill mapping: k-row = tid>>3, n-seg = (tid&7)*16 elems
    const int br_ = tid >> 3, bcseg = (tid & 7) * 16;
    const __nv_bfloat16* gBh = Bh + (size_t)br_ * 256 + bn + bcseg;
    const __nv_bfloat16* gBl = Bl + (size_t)br_ * 256 + bn + bcseg;

    char* const sAh = sm + ASH_OFF + ar * 80 + akseg * 2;
    char* const sAl = sm + ASL_OFF + ar * 80 + akseg * 2;
    char* const sBh = sm + BSH_OFF + br_ * 272 + bcseg * 2;
    char* const sBl = sm + BSL_OFF + br_ * 272 + bcseg * 2;

    float acc[2][8][4];
    #pragma unroll
    for (int i = 0; i < 2; i++)
        #pragma unroll
        for (int j = 0; j < 8; j++)
            #pragma unroll
            for (int k = 0; k < 4; k++) acc[i][j][k] = 0.f;

    // ldmatrix lane addresses
    const uint32_t aAddrBaseH = sb + ASH_OFF + (uint32_t)(warp_m + (lane & 15)) * 80 + (lane >> 4) * 16;
    const uint32_t aAddrBaseL = aAddrBaseH + (ASL_OFF - ASH_OFF);
    const int bg = lane >> 3;
    const uint32_t bAddrBaseH = sb + BSH_OFF + (uint32_t)((bg & 1) * 8 + (lane & 7)) * 272
                              + (uint32_t)(warp_n + (bg >> 1) * 8) * 2;
    const uint32_t bAddrBaseL = bAddrBaseH + (BSL_OFF - BSH_OFF);

    const uint4 z4 = make_uint4(0u, 0u, 0u, 0u);
    uint4 pAh0, pAh1, pAl0, pAl1, pBh0, pBh1, pBl0, pBl1;

    // prefetch chunk 0
    {
        pAh0 = ar_ok ? *reinterpret_cast<const uint4*>(gAh) : z4;
        pAh1 = ar_ok ? *reinterpret_cast<const uint4*>(gAh + 8) : z4;
        pAl0 = ar_ok ? *reinterpret_cast<const uint4*>(gAl) : z4;
        pAl1 = ar_ok ? *reinterpret_cast<const uint4*>(gAl + 8) : z4;
        pBh0 = *reinterpret_cast<const uint4*>(gBh);
        pBh1 = *reinterpret_cast<const uint4*>(gBh + 8);
        pBl0 = *reinterpret_cast<const uint4*>(gBl);
        pBl1 = *reinterpret_cast<const uint4*>(gBl + 8);
    }

    #pragma unroll 1
    for (int kc = 0; kc < 8; kc++) {
        // store prefetched chunk into smem
        *reinterpret_cast<uint4*>(sAh) = pAh0; *reinterpret_cast<uint4*>(sAh + 16) = pAh1;
        *reinterpret_cast<uint4*>(sAl) = pAl0; *reinterpret_cast<uint4*>(sAl + 16) = pAl1;
        *reinterpret_cast<uint4*>(sBh) = pBh0; *reinterpret_cast<uint4*>(sBh + 16) = pBh1;
        *reinterpret_cast<uint4*>(sBl) = pBl0; *reinterpret_cast<uint4*>(sBl + 16) = pBl1;
        __syncthreads();

        // prefetch next chunk (overlaps with mma below)
        if (kc < 7) {
            const int k1 = (kc + 1) * 32;
            pAh0 = ar_ok ? *reinterpret_cast<const uint4*>(gAh + k1) : z4;
            pAh1 = ar_ok ? *reinterpret_cast<const uint4*>(gAh + k1 + 8) : z4;
            pAl0 = ar_ok ? *reinterpret_cast<const uint4*>(gAl + k1) : z4;
            pAl1 = ar_ok ? *reinterpret_cast<const uint4*>(gAl + k1 + 8) : z4;
            const __nv_bfloat16* nBh = gBh + (size_t)k1 * 256;
            const __nv_bfloat16* nBl = gBl + (size_t)k1 * 256;
            pBh0 = *reinterpret_cast<const uint4*>(nBh);
            pBh1 = *reinterpret_cast<const uint4*>(nBh + 8);
            pBl0 = *reinterpret_cast<const uint4*>(nBl);
            pBl1 = *reinterpret_cast<const uint4*>(nBl + 8);
        }

        #pragma unroll
        for (int ks = 0; ks < 2; ks++) {
            uint32_t bh[4][4], bl[4][4];
            #pragma unroll
            for (int nt = 0; nt < 4; nt++) {
                uint32_t off = (uint32_t)(ks * 16) * 272 + (uint32_t)(nt * 16) * 2;
                ldsm_x4_t(bh[nt], bAddrBaseH + off);
                ldsm_x4_t(bl[nt], bAddrBaseL + off);
            }
            #pragma unroll
            for (int mt = 0; mt < 2; mt++) {
                uint32_t ah[4], al[4];
                uint32_t aoff = (uint32_t)(mt * 16) * 80 + (uint32_t)(ks * 32);
                ldsm_x4(ah, aAddrBaseH + aoff);
                ldsm_x4(al, aAddrBaseL + aoff);
                #pragma unroll
                for (int nt = 0; nt < 4; nt++) {
                    float* d0 = acc[mt][nt * 2];
                    float* d1 = acc[mt][nt * 2 + 1];
                    mma_bf16(d0[0], d0[1], d0[2], d0[3], ah, bh[nt][0], bh[nt][1]);
                    mma_bf16(d1[0], d1[1], d1[2], d1[3], ah, bh[nt][2], bh[nt][3]);
                    mma_bf16(d0[0], d0[1], d0[2], d0[3], ah, bl[nt][0], bl[nt][1]);
                    mma_bf16(d1[0], d1[1], d1[2], d1[3], ah, bl[nt][2], bl[nt][3]);
                    mma_bf16(d0[0], d0[1], d0[2], d0[3], al, bh[nt][0], bh[nt][1]);
                    mma_bf16(d1[0], d1[1], d1[2], d1[3], al, bh[nt][2], bh[nt][3]);
                }
            }
        }
        if (kc < 7) __syncthreads();
    }

    // ---- epilogue ----
    const int crow = lane >> 2, ccol = (lane & 3) * 2;
    #pragma unroll
    for (int mt = 0; mt < 2; mt++) {
        int row0 = bm + warp_m + mt * 16 + crow;
        #pragma unroll
        for (int nt8 = 0; nt8 < 8; nt8++) {
            int col = bn + warp_n + nt8 * 8 + ccol;
            float bx = bias[col], by = bias[col + 1];
            if (row0 < M) {
                float2 o = make_float2(acc[mt][nt8][0] + bx, acc[mt][nt8][1] + by);
                *reinterpret_cast<float2*>(Y + (size_t)row0 * 256 + col) = o;
            }
            if (row0 + 8 < M) {
                float2 o = make_float2(acc[mt][nt8][2] + bx, acc[mt][nt8][3] + by);
                *reinterpret_cast<float2*>(Y + (size_t)(row0 + 8) * 256 + col) = o;
            }
        }
    }
}

// ---------------- edge logits: warp per edge ----------------
__global__ void edge_logits_k(const int* __restrict__ ei,
                              const float* __restrict__ We, const float* __restrict__ att) {
    __shared__ float sWe[EDGE_DIM * HID];
    __shared__ float sAtt[HID];
    int tid = threadIdx.x;
    for (int i = tid; i < EDGE_DIM * HID; i += 256) sWe[i] = We[i];
    sAtt[tid] = att[tid];
    __syncthreads();
    int warp = tid >> 5, lane = tid & 31;
    int e = blockIdx.x * 8 + warp;
    if (e >= Ee) return;
    int src = ei[e], dst = ei[Ee + e];
    float a9 = (lane < EDGE_DIM) ? g_ea[e * EDGE_DIM + lane] : 0.f;
    float p[8];
    #pragma unroll
    for (int j = 0; j < 8; j++) {
        int ch = j * 32 + lane;
        float xe = 0.f;
        #pragma unroll
        for (int k = 0; k < EDGE_DIM; k++)
            xe += __shfl_sync(0xffffffffu, a9, k) * sWe[k * HID + ch];
        float v = g_xl[src * HID + ch] + g_xr[dst * HID + ch] + xe;
        v = (v > 0.f) ? v : 0.2f * v;
        p[j] = v * sAtt[j * 32 + lane];
    }
    #pragma unroll
    for (int off = 16; off; off >>= 1)
        #pragma unroll
        for (int j = 0; j < 8; j++) p[j] += __shfl_xor_sync(0xffffffffu, p[j], off);
    if (lane == 0) {
        #pragma unroll
        for (int j = 0; j < 8; j++) g_logits[e * 8 + j] = p[j];
    }
}

// ---------------- segment softmax + aggregate ----------------
__global__ void attn_agg_k(const int* __restrict__ ei, const float* __restrict__ bias) {
    int n = blockIdx.x;
    int h = threadIdx.x >> 5, lane = threadIdx.x & 31;
    int start = g_off[n], deg = g_off[n + 1] - start;
    int oidx = n * HID + h * 32 + lane;
    if (deg == 0) { g_out[oidx] = bias[h * 32 + lane]; return; }
    float m = -INFINITY;
    for (int i = lane; i < deg; i += 32)
        m = fmaxf(m, g_logits[g_elist[start + i] * 8 + h]);
    #pragma unroll
    for (int off = 16; off; off >>= 1) m = fmaxf(m, __shfl_xor_sync(0xffffffffu, m, off));
    float ssum = 0.f;
    for (int i = lane; i < deg; i += 32)
        ssum += expf(g_logits[g_elist[start + i] * 8 + h] - m);
    #pragma unroll
    for (int off = 16; off; off >>= 1) ssum += __shfl_xor_sync(0xffffffffu, ssum, off);
    float inv = 1.f / (ssum + 1e-16f);
    float acc = 0.f;
    for (int i = 0; i < deg; i++) {
        int e = g_elist[start + i];
        float w = expf(g_logits[e * 8 + h] - m) * inv;
        acc += w * g_xl[ei[e] * HID + h * 32 + lane];
    }
    g_out[oidx] = acc + bias[h * 32 + lane];
}

// ---------------- BatchNorm ----------------
__global__ void bn_stats_k(const float* __restrict__ v) {
    int c = threadIdx.x;
    double s = 0.0, s2 = 0.0;
    for (int n = blockIdx.x; n < Nn; n += gridDim.x) {
        float x = v[n * HID + c];
        s += x; s2 += (double)x * x;
    }
    atomicAdd(&g_red[c], s);
    atomicAdd(&g_red[256 + c], s2);
}

__global__ void bn_final_k(const float* __restrict__ gamma, const float* __restrict__ beta) {
    int c = threadIdx.x;
    double mu = g_red[c] / (double)Nn;
    double var = g_red[256 + c] / (double)Nn - mu * mu;
    float scale = gamma[c] * rsqrtf((float)var + 1e-5f);
    g_bnp[c] = scale;
    g_bnp[256 + c] = beta[c] - (float)mu * scale;
    g_red[c] = 0.0; g_red[256 + c] = 0.0;
}

// act: 0 = elu, 1 = relu; also emits bf16 hi/lo for the next GEMM
__global__ void bn_apply_k(const float* __restrict__ v, float* __restrict__ o, int act) {
    int c = threadIdx.x;
    int idx = blockIdx.x * HID + c;
    float y = v[idx] * g_bnp[c] + g_bnp[256 + c];
    float r = act ? fmaxf(y, 0.f) : ((y > 0.f) ? y : expm1f(y));
    o[idx] = r;
    __nv_bfloat16 hi, lo;
    split1(r, hi, lo);
    g_hh[idx] = hi; g_hl[idx] = lo;
}

// ---------------- final projection ----------------
__global__ void proj3_k(const float* __restrict__ W, const float* __restrict__ b,
                        float* __restrict__ out) {
    int idx = blockIdx.x * 256 + threadIdx.x;
    if (idx >= Nn * 3) return;
    int n = idx / 3, o = idx % 3;
    float acc = b[o];
    const float* hrow = &g_h[n * HID];
    #pragma unroll 8
    for (int k = 0; k < HID; k++) acc += hrow[k] * W[k * 3 + o];
    out[idx] = acc;
}

// ---------------- launch ----------------
extern "C" void kernel_launch(void* const* d_in, const int* in_sizes, int n_in,
                              void* d_out, int out_size) {
    const float* x         = (const float*)d_in[0];
    const float* edge_attr = (const float*)d_in[1];
    const int*   ei        = (const int*)  d_in[2];
    const float* lift_W    = (const float*)d_in[3];
    const float* lift_b    = (const float*)d_in[4];
    const float* Wl        = (const float*)d_in[5];
    const float* bl        = (const float*)d_in[6];
    const float* Wr        = (const float*)d_in[7];
    const float* br        = (const float*)d_in[8];
    const float* We        = (const float*)d_in[9];
    const float* att       = (const float*)d_in[10];
    const float* conv_bias = (const float*)d_in[11];
    const float* bn_gamma  = (const float*)d_in[12];
    const float* bn_beta   = (const float*)d_in[13];
    const float* p1_W      = (const float*)d_in[14];
    const float* p1_b      = (const float*)d_in[15];
    const float* pbn1_g    = (const float*)d_in[16];
    const float* pbn1_b    = (const float*)d_in[17];
    const float* p2_W      = (const float*)d_in[18];
    const float* p2_b      = (const float*)d_in[19];
    const float* pbn2_g    = (const float*)d_in[20];
    const float* pbn2_b    = (const float*)d_in[21];
    const float* p3_W      = (const float*)d_in[22];
    const float* p3_b      = (const float*)d_in[23];
    float* out = (float*)d_out;

    float* d_h = nullptr; float* d_xl = nullptr; float* d_xr = nullptr; float* d_o = nullptr;
    __nv_bfloat16* d_Wbh = nullptr; __nv_bfloat16* d_Wbl = nullptr;
    cudaGetSymbolAddress((void**)&d_h,  g_h);
    cudaGetSymbolAddress((void**)&d_xl, g_xl);
    cudaGetSymbolAddress((void**)&d_xr, g_xr);
    cudaGetSymbolAddress((void**)&d_o,  g_out);
    cudaGetSymbolAddress((void**)&d_Wbh, g_Wbh);
    cudaGetSymbolAddress((void**)&d_Wbl, g_Wbl);

    const dim3 grid2((Nn + 127) / 128, 2, 2);  // dual gemm
    const dim3 grid1((Nn + 127) / 128, 2, 1);  // single gemm
    const int WSL = HID * HID;  // weight slot stride

    // 1: weight pre-conversion
    wconv_k<<<12 * 256, 256>>>(Wl, Wr, p1_W, p2_W);
    // 2: zero reductions
    zero_red_k<<<1, 512>>>();
    // 3: lift (writes fp32 + bf16 h)
    lift_k<<<Nn, HID>>>(x, lift_W, lift_b);
    // 4: first gemm pair  <-- profiled slot
    hgemm_k<<<grid2, 256>>>(d_Wbh + 0 * WSL, d_Wbl + 0 * WSL, bl, d_xl,
                            d_Wbh + 5 * WSL, d_Wbl + 5 * WSL, br, d_xr, Nn);
    // edge-attr normalization
    ea_stats_k<<<64, 256>>>(edge_attr);
    ea_final_k<<<1, 32>>>();
    ea_norm_k<<<(Ee * EDGE_DIM + 255) / 256, 256>>>(edge_attr);
    // CSR by destination
    zero_cnt_k<<<(Nn + 256) / 256, 256>>>();
    hist_k<<<Ee / 256, 256>>>(ei);
    scan_k<<<1, 1024>>>();
    fill_k<<<Ee / 256, 256>>>(ei);

    for (int t = 0; t < Tt; t++) {
        if (t > 0) {
            hgemm_k<<<grid2, 256>>>(d_Wbh + t * WSL, d_Wbl + t * WSL, bl + t * HID, d_xl,
                                    d_Wbh + (5 + t) * WSL, d_Wbl + (5 + t) * WSL, br + t * HID, d_xr, Nn);
        }
        edge_logits_k<<<Ee / 8, 256>>>(ei, We + t * EDGE_DIM * HID, att + t * HEADS * Cc);
        attn_agg_k<<<Nn, 256>>>(ei, conv_bias + t * HID);
        bn_stats_k<<<80, 256>>>(d_o);
        bn_final_k<<<1, 256>>>(bn_gamma + t * HID, bn_beta + t * HID);
        bn_apply_k<<<Nn, HID>>>(d_o, d_h, 0);
    }

    // projection MLP
    hgemm_k<<<grid1, 256>>>(d_Wbh + 10 * WSL, d_Wbl + 10 * WSL, p1_b, d_o,
                            d_Wbh + 10 * WSL, d_Wbl + 10 * WSL, p1_b, d_o, Nn);
    bn_stats_k<<<80, 256>>>(d_o);
    bn_final_k<<<1, 256>>>(pbn1_g, pbn1_b);
    bn_apply_k<<<Nn, HID>>>(d_o, d_h, 1);

    hgemm_k<<<grid1, 256>>>(d_Wbh + 11 * WSL, d_Wbl + 11 * WSL, p2_b, d_o,
                            d_Wbh + 11 * WSL, d_Wbl + 11 * WSL, p2_b, d_o, Nn);
    bn_stats_k<<<80, 256>>>(d_o);
    bn_final_k<<<1, 256>>>(pbn2_g, pbn2_b);
    bn_apply_k<<<Nn, HID>>>(d_o, d_h, 1);

    proj3_k<<<(Nn * 3 + 255) / 256, 256>>>(p3_W, p3_b, out);
}

// round 11
// speedup vs baseline: 1.5610x; 1.2091x over previous
#include <cuda_runtime.h>
#include <cuda_bf16.h>
#include <math.h>
#include <stdint.h>

#define Nn 10000
#define Ee 160000
#define HID 256
#define HEADS 8
#define Cc 32
#define Tt 5
#define EDGE_DIM 9
#define DCH 256   // edges per softmax chunk

// ---------------- scratch (static device globals; no allocation) ----------------
__device__ float g_ea[Ee * EDGE_DIM];
__device__ float g_h[Nn * HID];
__device__ float g_xl[Nn * HID];
__device__ float g_xr[Nn * HID];
__device__ float g_out[Nn * HID];
__device__ int   g_cnt[Nn + 1];
__device__ int   g_off[Nn + 1];
__device__ int   g_cur[Nn];
__device__ int   g_elist[Ee];
__device__ double g_red[512];
__device__ float g_bnp[512];
__device__ float g_eap[2 * EDGE_DIM];
// bf16 hi/lo copies for tensor-core GEMM
__device__ __nv_bfloat16 g_hh[Nn * HID];
__device__ __nv_bfloat16 g_hl[Nn * HID];
__device__ __nv_bfloat16 g_Wbh[12 * HID * HID];
__device__ __nv_bfloat16 g_Wbl[12 * HID * HID];

// ---------------- utility ----------------
__global__ void zero_red_k() { int i = threadIdx.x; if (i < 512) g_red[i] = 0.0; }
__global__ void zero_cnt_k() { int i = blockIdx.x * 256 + threadIdx.x; if (i <= Nn) g_cnt[i] = 0; }

__device__ __forceinline__ void split1(float x, __nv_bfloat16& hi, __nv_bfloat16& lo) {
    hi = __float2bfloat16_rn(x);
    lo = __float2bfloat16_rn(x - __bfloat162float(hi));
}

// ---------------- weight pre-conversion: 12 slots of 256x256 ----------------
__global__ void wconv_k(const float* __restrict__ Wl, const float* __restrict__ Wr,
                        const float* __restrict__ p1, const float* __restrict__ p2) {
    int idx = blockIdx.x * 256 + threadIdx.x;
    int slot = idx >> 16, e = idx & 65535;
    float v;
    if (slot < 5)       v = Wl[slot * 65536 + e];
    else if (slot < 10) v = Wr[(slot - 5) * 65536 + e];
    else if (slot == 10) v = p1[e];
    else                 v = p2[e];
    __nv_bfloat16 hi, lo;
    split1(v, hi, lo);
    g_Wbh[idx] = hi; g_Wbl[idx] = lo;
}

// ---------------- edge-attr normalization ----------------
__global__ void ea_stats_k(const float* __restrict__ ea) {
    __shared__ double ss[EDGE_DIM], ss2[EDGE_DIM];
    if (threadIdx.x < EDGE_DIM) { ss[threadIdx.x] = 0.0; ss2[threadIdx.x] = 0.0; }
    __syncthreads();
    double ls[EDGE_DIM] = {0}, ls2[EDGE_DIM] = {0};
    for (int e = blockIdx.x * blockDim.x + threadIdx.x; e < Ee; e += gridDim.x * blockDim.x) {
        #pragma unroll
        for (int k = 0; k < EDGE_DIM; k++) {
            float x = ea[e * EDGE_DIM + k];
            ls[k] += x; ls2[k] += (double)x * x;
        }
    }
    #pragma unroll
    for (int k = 0; k < EDGE_DIM; k++) { atomicAdd(&ss[k], ls[k]); atomicAdd(&ss2[k], ls2[k]); }
    __syncthreads();
    if (threadIdx.x < EDGE_DIM) {
        atomicAdd(&g_red[threadIdx.x], ss[threadIdx.x]);
        atomicAdd(&g_red[256 + threadIdx.x], ss2[threadIdx.x]);
    }
}

__global__ void ea_final_k() {
    int c = threadIdx.x;
    if (c < EDGE_DIM) {
        double mu = g_red[c] / (double)Ee;
        double var = g_red[256 + c] / (double)Ee - mu * mu;
        double sd = sqrt(var > 0.0 ? var : 0.0);
        g_eap[c] = (float)mu;
        g_eap[EDGE_DIM + c] = (float)(1.0 / (sd + 1e-8));
        g_red[c] = 0.0; g_red[256 + c] = 0.0;
    }
}

__global__ void ea_norm_k(const float* __restrict__ ea) {
    int idx = blockIdx.x * 256 + threadIdx.x;
    if (idx < Ee * EDGE_DIM) {
        int c = idx % EDGE_DIM;
        g_ea[idx] = (ea[idx] - g_eap[c]) * g_eap[EDGE_DIM + c];
    }
}

// ---------------- lift ----------------
__global__ void lift_k(const float* __restrict__ x, const float* __restrict__ W,
                       const float* __restrict__ b) {
    int n = blockIdx.x;
    int c = threadIdx.x;
    float acc = b[c];
    #pragma unroll
    for (int k = 0; k < 10; k++) acc += x[n * 10 + k] * W[k * HID + c];
    float h = fmaxf(acc, 0.f);
    g_h[n * HID + c] = h;
    __nv_bfloat16 hi, lo;
    split1(h, hi, lo);
    g_hh[n * HID + c] = hi; g_hl[n * HID + c] = lo;
}

// ---------------- CSR build ----------------
__global__ void hist_k(const int* __restrict__ ei) {
    int e = blockIdx.x * 256 + threadIdx.x;
    if (e < Ee) atomicAdd(&g_cnt[ei[Ee + e]], 1);
}

__global__ void scan_k() {
    __shared__ int partial[1024];
    int tid = threadIdx.x;
    const int PER = 10;
    int base = tid * PER;
    int loc[PER];
    int s = 0;
    #pragma unroll
    for (int i = 0; i < PER; i++) {
        int n = base + i;
        int v = (n < Nn) ? g_cnt[n] : 0;
        loc[i] = s; s += v;
    }
    partial[tid] = s;
    __syncthreads();
    for (int off = 1; off < 1024; off <<= 1) {
        int v = (tid >= off) ? partial[tid - off] : 0;
        __syncthreads();
        partial[tid] += v;
        __syncthreads();
    }
    int offset = (tid > 0) ? partial[tid - 1] : 0;
    #pragma unroll
    for (int i = 0; i < PER; i++) {
        int n = base + i;
        if (n < Nn) { g_off[n] = offset + loc[i]; g_cur[n] = offset + loc[i]; }
    }
    if (tid == 1023) g_off[Nn] = partial[1023];
}

__global__ void fill_k(const int* __restrict__ ei) {
    int e = blockIdx.x * 256 + threadIdx.x;
    if (e < Ee) {
        int pos = atomicAdd(&g_cur[ei[Ee + e]], 1);
        g_elist[pos] = e;
    }
}

// ================= bf16-split HMMA GEMM (preconverted inputs) =================
#define ASH_OFF 0
#define ASL_OFF 10240
#define BSH_OFF 20480
#define BSL_OFF 29184
#define GSM_TOT 37888

__device__ __forceinline__ uint32_t smem_u32(const void* p) {
    uint32_t a;
    asm("{ .reg .u64 t; cvta.to.shared.u64 t, %1; cvt.u32.u64 %0, t; }" : "=r"(a) : "l"(p));
    return a;
}
__device__ __forceinline__ void ldsm_x4(uint32_t* r, uint32_t addr) {
    asm volatile("ldmatrix.sync.aligned.m8n8.x4.shared.b16 {%0,%1,%2,%3}, [%4];"
                 : "=r"(r[0]), "=r"(r[1]), "=r"(r[2]), "=r"(r[3]) : "r"(addr));
}
__device__ __forceinline__ void ldsm_x4_t(uint32_t* r, uint32_t addr) {
    asm volatile("ldmatrix.sync.aligned.m8n8.x4.trans.shared.b16 {%0,%1,%2,%3}, [%4];"
                 : "=r"(r[0]), "=r"(r[1]), "=r"(r[2]), "=r"(r[3]) : "r"(addr));
}
__device__ __forceinline__ void mma_bf16(float& d0, float& d1, float& d2, float& d3,
                                         const uint32_t* a, uint32_t b0, uint32_t b1) {
    asm volatile(
        "mma.sync.aligned.m16n8k16.row.col.f32.bf16.bf16.f32 "
        "{%0,%1,%2,%3}, {%4,%5,%6,%7}, {%8,%9}, {%0,%1,%2,%3};"
        : "+f"(d0), "+f"(d1), "+f"(d2), "+f"(d3)
        : "r"(a[0]), "r"(a[1]), "r"(a[2]), "r"(a[3]), "r"(b0), "r"(b1));
}

__global__ void __launch_bounds__(256)
hgemm_k(const __nv_bfloat16* __restrict__ Bh0, const __nv_bfloat16* __restrict__ Bl0,
        const float* __restrict__ b0, float* __restrict__ Y0,
        const __nv_bfloat16* __restrict__ Bh1, const __nv_bfloat16* __restrict__ Bl1,
        const float* __restrict__ b1, float* __restrict__ Y1,
        int M) {
    __shared__ __align__(16) char sm[GSM_TOT];
    const uint32_t sb = smem_u32(sm);
    const int tid = threadIdx.x;
    const int wid = tid >> 5, lane = tid & 31;
    const int bm = blockIdx.x * 128, bn = blockIdx.y * 128;
    const __nv_bfloat16* Bh  = blockIdx.z ? Bh1 : Bh0;
    const __nv_bfloat16* Bl  = blockIdx.z ? Bl1 : Bl0;
    const float* bias        = blockIdx.z ? b1 : b0;
    float*       Y           = blockIdx.z ? Y1 : Y0;

    const int warp_m = (wid >> 1) * 32;
    const int warp_n = (wid & 1) * 64;

    const int ar = tid >> 1, akseg = (tid & 1) * 16;
    const bool ar_ok = (bm + ar) < M;
    const __nv_bfloat16* gAh = g_hh + (size_t)(bm + ar) * 256 + akseg;
    const __nv_bfloat16* gAl = g_hl + (size_t)(bm + ar) * 256 + akseg;
    const int br_ = tid >> 3, bcseg = (tid & 7) * 16;
    const __nv_bfloat16* gBh = Bh + (size_t)br_ * 256 + bn + bcseg;
    const __nv_bfloat16* gBl = Bl + (size_t)br_ * 256 + bn + bcseg;

    char* const sAh = sm + ASH_OFF + ar * 80 + akseg * 2;
    char* const sAl = sm + ASL_OFF + ar * 80 + akseg * 2;
    char* const sBh = sm + BSH_OFF + br_ * 272 + bcseg * 2;
    char* const sBl = sm + BSL_OFF + br_ * 272 + bcseg * 2;

    float acc[2][8][4];
    #pragma unroll
    for (int i = 0; i < 2; i++)
        #pragma unroll
        for (int j = 0; j < 8; j++)
            #pragma unroll
            for (int k = 0; k < 4; k++) acc[i][j][k] = 0.f;

    const uint32_t aAddrBaseH = sb + ASH_OFF + (uint32_t)(warp_m + (lane & 15)) * 80 + (lane >> 4) * 16;
    const uint32_t aAddrBaseL = aAddrBaseH + (ASL_OFF - ASH_OFF);
    const int bg = lane >> 3;
    const uint32_t bAddrBaseH = sb + BSH_OFF + (uint32_t)((bg & 1) * 8 + (lane & 7)) * 272
                              + (uint32_t)(warp_n + (bg >> 1) * 8) * 2;
    const uint32_t bAddrBaseL = bAddrBaseH + (BSL_OFF - BSH_OFF);

    const uint4 z4 = make_uint4(0u, 0u, 0u, 0u);
    uint4 pAh0, pAh1, pAl0, pAl1, pBh0, pBh1, pBl0, pBl1;

    {
        pAh0 = ar_ok ? *reinterpret_cast<const uint4*>(gAh) : z4;
        pAh1 = ar_ok ? *reinterpret_cast<const uint4*>(gAh + 8) : z4;
        pAl0 = ar_ok ? *reinterpret_cast<const uint4*>(gAl) : z4;
        pAl1 = ar_ok ? *reinterpret_cast<const uint4*>(gAl + 8) : z4;
        pBh0 = *reinterpret_cast<const uint4*>(gBh);
        pBh1 = *reinterpret_cast<const uint4*>(gBh + 8);
        pBl0 = *reinterpret_cast<const uint4*>(gBl);
        pBl1 = *reinterpret_cast<const uint4*>(gBl + 8);
    }

    #pragma unroll 1
    for (int kc = 0; kc < 8; kc++) {
        *reinterpret_cast<uint4*>(sAh) = pAh0; *reinterpret_cast<uint4*>(sAh + 16) = pAh1;
        *reinterpret_cast<uint4*>(sAl) = pAl0; *reinterpret_cast<uint4*>(sAl + 16) = pAl1;
        *reinterpret_cast<uint4*>(sBh) = pBh0; *reinterpret_cast<uint4*>(sBh + 16) = pBh1;
        *reinterpret_cast<uint4*>(sBl) = pBl0; *reinterpret_cast<uint4*>(sBl + 16) = pBl1;
        __syncthreads();

        if (kc < 7) {
            const int k1 = (kc + 1) * 32;
            pAh0 = ar_ok ? *reinterpret_cast<const uint4*>(gAh + k1) : z4;
            pAh1 = ar_ok ? *reinterpret_cast<const uint4*>(gAh + k1 + 8) : z4;
            pAl0 = ar_ok ? *reinterpret_cast<const uint4*>(gAl + k1) : z4;
            pAl1 = ar_ok ? *reinterpret_cast<const uint4*>(gAl + k1 + 8) : z4;
            const __nv_bfloat16* nBh = gBh + (size_t)k1 * 256;
            const __nv_bfloat16* nBl = gBl + (size_t)k1 * 256;
            pBh0 = *reinterpret_cast<const uint4*>(nBh);
            pBh1 = *reinterpret_cast<const uint4*>(nBh + 8);
            pBl0 = *reinterpret_cast<const uint4*>(nBl);
            pBl1 = *reinterpret_cast<const uint4*>(nBl + 8);
        }

        #pragma unroll
        for (int ks = 0; ks < 2; ks++) {
            uint32_t bh[4][4], bl[4][4];
            #pragma unroll
            for (int nt = 0; nt < 4; nt++) {
                uint32_t off = (uint32_t)(ks * 16) * 272 + (uint32_t)(nt * 16) * 2;
                ldsm_x4_t(bh[nt], bAddrBaseH + off);
                ldsm_x4_t(bl[nt], bAddrBaseL + off);
            }
            #pragma unroll
            for (int mt = 0; mt < 2; mt++) {
                uint32_t ah[4], al[4];
                uint32_t aoff = (uint32_t)(mt * 16) * 80 + (uint32_t)(ks * 32);
                ldsm_x4(ah, aAddrBaseH + aoff);
                ldsm_x4(al, aAddrBaseL + aoff);
                #pragma unroll
                for (int nt = 0; nt < 4; nt++) {
                    float* d0 = acc[mt][nt * 2];
                    float* d1 = acc[mt][nt * 2 + 1];
                    mma_bf16(d0[0], d0[1], d0[2], d0[3], ah, bh[nt][0], bh[nt][1]);
                    mma_bf16(d1[0], d1[1], d1[2], d1[3], ah, bh[nt][2], bh[nt][3]);
                    mma_bf16(d0[0], d0[1], d0[2], d0[3], ah, bl[nt][0], bl[nt][1]);
                    mma_bf16(d1[0], d1[1], d1[2], d1[3], ah, bl[nt][2], bl[nt][3]);
                    mma_bf16(d0[0], d0[1], d0[2], d0[3], al, bh[nt][0], bh[nt][1]);
                    mma_bf16(d1[0], d1[1], d1[2], d1[3], al, bh[nt][2], bh[nt][3]);
                }
            }
        }
        if (kc < 7) __syncthreads();
    }

    const int crow = lane >> 2, ccol = (lane & 3) * 2;
    #pragma unroll
    for (int mt = 0; mt < 2; mt++) {
        int row0 = bm + warp_m + mt * 16 + crow;
        #pragma unroll
        for (int nt8 = 0; nt8 < 8; nt8++) {
            int col = bn + warp_n + nt8 * 8 + ccol;
            float bx = bias[col], by = bias[col + 1];
            if (row0 < M) {
                float2 o = make_float2(acc[mt][nt8][0] + bx, acc[mt][nt8][1] + by);
                *reinterpret_cast<float2*>(Y + (size_t)row0 * 256 + col) = o;
            }
            if (row0 + 8 < M) {
                float2 o = make_float2(acc[mt][nt8][2] + bx, acc[mt][nt8][3] + by);
                *reinterpret_cast<float2*>(Y + (size_t)(row0 + 8) * 256 + col) = o;
            }
        }
    }
}

// ================= fused GATv2 attention: logits + segment softmax + aggregate =================
// Block per destination node, 128 threads (4 warps).
// Phase A: warp-per-edge computes 8 head logits (We/att in registers, xr[dst] in smem).
// Phase B: each warp owns 2 heads; online softmax across chunks + unrolled aggregation.
__global__ void __launch_bounds__(128)
attn_fused_k(const int* __restrict__ ei, const float* __restrict__ We_,
             const float* __restrict__ att, const float* __restrict__ bias) {
    __shared__ float s_xr[256];
    __shared__ float s_lw[8][260];   // logits -> weights (padded: 260%32=4 avoids write conflicts)
    __shared__ int   s_src[DCH];

    const int n = blockIdx.x;
    const int tid = threadIdx.x, wid = tid >> 5, lane = tid & 31;
    const int start = g_off[n], deg = g_off[n + 1] - start;

    // register We (each lane: channels lane*8..lane*8+7) and att
    float rWe[9][8], rAtt[8];
    {
        const float4* w4 = reinterpret_cast<const float4*>(We_);
        #pragma unroll
        for (int k = 0; k < 9; k++) {
            float4 a = w4[k * 64 + lane * 2];
            float4 b = w4[k * 64 + lane * 2 + 1];
            rWe[k][0] = a.x; rWe[k][1] = a.y; rWe[k][2] = a.z; rWe[k][3] = a.w;
            rWe[k][4] = b.x; rWe[k][5] = b.y; rWe[k][6] = b.z; rWe[k][7] = b.w;
        }
        const float4* a4 = reinterpret_cast<const float4*>(att);
        float4 a = a4[lane * 2], b = a4[lane * 2 + 1];
        rAtt[0] = a.x; rAtt[1] = a.y; rAtt[2] = a.z; rAtt[3] = a.w;
        rAtt[4] = b.x; rAtt[5] = b.y; rAtt[6] = b.z; rAtt[7] = b.w;
    }
    // xr row of this node into smem
    s_xr[tid] = g_xr[n * 256 + tid];
    s_xr[tid + 128] = g_xr[n * 256 + tid + 128];
    __syncthreads();

    float m[2] = {-INFINITY, -INFINITY};
    float den[2] = {0.f, 0.f};
    float acc[2] = {0.f, 0.f};

    for (int c0 = 0; c0 < deg; c0 += DCH) {
        const int cnt = min(DCH, deg - c0);

        // ---- Phase A: logits for this chunk ----
        for (int i0 = wid; i0 < cnt; i0 += 4) {
            int e = g_elist[start + c0 + i0];
            int src = __ldg(ei + e);
            if (lane == 0) s_src[i0] = src;
            float a9 = (lane < EDGE_DIM) ? g_ea[e * EDGE_DIM + lane] : 0.f;
            const float4* xl4 = reinterpret_cast<const float4*>(g_xl + (size_t)src * 256);
            float4 x0 = xl4[lane * 2], x1 = xl4[lane * 2 + 1];
            const float4* r4 = reinterpret_cast<const float4*>(s_xr);
            float4 r0 = r4[lane * 2], r1 = r4[lane * 2 + 1];
            float v[8];
            v[0] = x0.x + r0.x; v[1] = x0.y + r0.y; v[2] = x0.z + r0.z; v[3] = x0.w + r0.w;
            v[4] = x1.x + r1.x; v[5] = x1.y + r1.y; v[6] = x1.z + r1.z; v[7] = x1.w + r1.w;
            #pragma unroll
            for (int k = 0; k < EDGE_DIM; k++) {
                float eak = __shfl_sync(0xffffffffu, a9, k);
                #pragma unroll
                for (int c = 0; c < 8; c++) v[c] = fmaf(eak, rWe[k][c], v[c]);
            }
            float p = 0.f;
            #pragma unroll
            for (int c = 0; c < 8; c++) {
                float t = v[c] > 0.f ? v[c] : 0.2f * v[c];
                p = fmaf(t, rAtt[c], p);
            }
            p += __shfl_xor_sync(0xffffffffu, p, 1);
            p += __shfl_xor_sync(0xffffffffu, p, 2);
            if ((lane & 3) == 0) s_lw[lane >> 2][i0] = p;
        }
        __syncthreads();

        // ---- Phase B: online softmax + aggregate (warp owns heads wid, wid+4) ----
        #pragma unroll
        for (int j = 0; j < 2; j++) {
            const int h = wid + 4 * j;
            float cm = -INFINITY;
            for (int i = lane; i < cnt; i += 32) cm = fmaxf(cm, s_lw[h][i]);
            #pragma unroll
            for (int o = 16; o; o >>= 1) cm = fmaxf(cm, __shfl_xor_sync(0xffffffffu, cm, o));
            float mn = fmaxf(m[j], cm);
            float sc = expf(m[j] - mn);
            acc[j] *= sc; den[j] *= sc; m[j] = mn;
            float dp = 0.f;
            for (int i = lane; i < cnt; i += 32) {
                float w = expf(s_lw[h][i] - mn);
                s_lw[h][i] = w;
                dp += w;
            }
            #pragma unroll
            for (int o = 16; o; o >>= 1) dp += __shfl_xor_sync(0xffffffffu, dp, o);
            den[j] += dp;
            const float* xlh = g_xl + h * 32 + lane;
            int i = 0;
            for (; i + 4 <= cnt; i += 4) {
                float w0 = s_lw[h][i],     w1 = s_lw[h][i + 1];
                float w2 = s_lw[h][i + 2], w3 = s_lw[h][i + 3];
                int s0 = s_src[i], s1 = s_src[i + 1], s2 = s_src[i + 2], s3 = s_src[i + 3];
                acc[j] += w0 * xlh[(size_t)s0 * 256] + w1 * xlh[(size_t)s1 * 256]
                        + w2 * xlh[(size_t)s2 * 256] + w3 * xlh[(size_t)s3 * 256];
            }
            for (; i < cnt; i++) acc[j] += s_lw[h][i] * xlh[(size_t)s_src[i] * 256];
        }
        __syncthreads();
    }

    #pragma unroll
    for (int j = 0; j < 2; j++) {
        const int h = wid + 4 * j, oc = h * 32 + lane;
        float o = (deg == 0) ? bias[oc] : acc[j] / (den[j] + 1e-16f) + bias[oc];
        g_out[n * 256 + oc] = o;
    }
}

// ---------------- BatchNorm ----------------
__global__ void bn_stats_k(const float* __restrict__ v) {
    int c = threadIdx.x;
    double s = 0.0, s2 = 0.0;
    for (int n = blockIdx.x; n < Nn; n += gridDim.x) {
        float x = v[n * HID + c];
        s += x; s2 += (double)x * x;
    }
    atomicAdd(&g_red[c], s);
    atomicAdd(&g_red[256 + c], s2);
}

__global__ void bn_final_k(const float* __restrict__ gamma, const float* __restrict__ beta) {
    int c = threadIdx.x;
    double mu = g_red[c] / (double)Nn;
    double var = g_red[256 + c] / (double)Nn - mu * mu;
    float scale = gamma[c] * rsqrtf((float)var + 1e-5f);
    g_bnp[c] = scale;
    g_bnp[256 + c] = beta[c] - (float)mu * scale;
    g_red[c] = 0.0; g_red[256 + c] = 0.0;
}

// act: 0 = elu, 1 = relu; also emits bf16 hi/lo for the next GEMM
__global__ void bn_apply_k(const float* __restrict__ v, float* __restrict__ o, int act) {
    int c = threadIdx.x;
    int idx = blockIdx.x * HID + c;
    float y = v[idx] * g_bnp[c] + g_bnp[256 + c];
    float r = act ? fmaxf(y, 0.f) : ((y > 0.f) ? y : expm1f(y));
    o[idx] = r;
    __nv_bfloat16 hi, lo;
    split1(r, hi, lo);
    g_hh[idx] = hi; g_hl[idx] = lo;
}

// ---------------- final projection ----------------
__global__ void proj3_k(const float* __restrict__ W, const float* __restrict__ b,
                        float* __restrict__ out) {
    int idx = blockIdx.x * 256 + threadIdx.x;
    if (idx >= Nn * 3) return;
    int n = idx / 3, o = idx % 3;
    float acc = b[o];
    const float* hrow = &g_h[n * HID];
    #pragma unroll 8
    for (int k = 0; k < HID; k++) acc += hrow[k] * W[k * 3 + o];
    out[idx] = acc;
}

// ---------------- launch ----------------
extern "C" void kernel_launch(void* const* d_in, const int* in_sizes, int n_in,
                              void* d_out, int out_size) {
    const float* x         = (const float*)d_in[0];
    const float* edge_attr = (const float*)d_in[1];
    const int*   ei        = (const int*)  d_in[2];
    const float* lift_W    = (const float*)d_in[3];
    const float* lift_b    = (const float*)d_in[4];
    const float* Wl        = (const float*)d_in[5];
    const float* bl        = (const float*)d_in[6];
    const float* Wr        = (const float*)d_in[7];
    const float* br        = (const float*)d_in[8];
    const float* We        = (const float*)d_in[9];
    const float* att       = (const float*)d_in[10];
    const float* conv_bias = (const float*)d_in[11];
    const float* bn_gamma  = (const float*)d_in[12];
    const float* bn_beta   = (const float*)d_in[13];
    const float* p1_W      = (const float*)d_in[14];
    const float* p1_b      = (const float*)d_in[15];
    const float* pbn1_g    = (const float*)d_in[16];
    const float* pbn1_b    = (const float*)d_in[17];
    const float* p2_W      = (const float*)d_in[18];
    const float* p2_b      = (const float*)d_in[19];
    const float* pbn2_g    = (const float*)d_in[20];
    const float* pbn2_b    = (const float*)d_in[21];
    const float* p3_W      = (const float*)d_in[22];
    const float* p3_b      = (const float*)d_in[23];
    float* out = (float*)d_out;

    float* d_h = nullptr; float* d_xl = nullptr; float* d_xr = nullptr; float* d_o = nullptr;
    __nv_bfloat16* d_Wbh = nullptr; __nv_bfloat16* d_Wbl = nullptr;
    cudaGetSymbolAddress((void**)&d_h,  g_h);
    cudaGetSymbolAddress((void**)&d_xl, g_xl);
    cudaGetSymbolAddress((void**)&d_xr, g_xr);
    cudaGetSymbolAddress((void**)&d_o,  g_out);
    cudaGetSymbolAddress((void**)&d_Wbh, g_Wbh);
    cudaGetSymbolAddress((void**)&d_Wbl, g_Wbl);

    const dim3 grid2((Nn + 127) / 128, 2, 2);  // dual gemm
    const dim3 grid1((Nn + 127) / 128, 2, 1);  // single gemm
    const int WSL = HID * HID;

    // 1: weight pre-conversion
    wconv_k<<<12 * 256, 256>>>(Wl, Wr, p1_W, p2_W);
    // 2: zero reductions
    zero_red_k<<<1, 512>>>();
    // 3: lift (writes fp32 + bf16 h)
    lift_k<<<Nn, HID>>>(x, lift_W, lift_b);
    // 4: first gemm pair  <-- profiled slot
    hgemm_k<<<grid2, 256>>>(d_Wbh + 0 * WSL, d_Wbl + 0 * WSL, bl, d_xl,
                            d_Wbh + 5 * WSL, d_Wbl + 5 * WSL, br, d_xr, Nn);
    // edge-attr normalization
    ea_stats_k<<<64, 256>>>(edge_attr);
    ea_final_k<<<1, 32>>>();
    ea_norm_k<<<(Ee * EDGE_DIM + 255) / 256, 256>>>(edge_attr);
    // CSR by destination
    zero_cnt_k<<<(Nn + 256) / 256, 256>>>();
    hist_k<<<Ee / 256, 256>>>(ei);
    scan_k<<<1, 1024>>>();
    fill_k<<<Ee / 256, 256>>>(ei);

    for (int t = 0; t < Tt; t++) {
        if (t > 0) {
            hgemm_k<<<grid2, 256>>>(d_Wbh + t * WSL, d_Wbl + t * WSL, bl + t * HID, d_xl,
                                    d_Wbh + (5 + t) * WSL, d_Wbl + (5 + t) * WSL, br + t * HID, d_xr, Nn);
        }
        attn_fused_k<<<Nn, 128>>>(ei, We + t * EDGE_DIM * HID, att + t * HEADS * Cc,
                                  conv_bias + t * HID);
        bn_stats_k<<<80, 256>>>(d_o);
        bn_final_k<<<1, 256>>>(bn_gamma + t * HID, bn_beta + t * HID);
        bn_apply_k<<<Nn, HID>>>(d_o, d_h, 0);
    }

    // projection MLP
    hgemm_k<<<grid1, 256>>>(d_Wbh + 10 * WSL, d_Wbl + 10 * WSL, p1_b, d_o,
                            d_Wbh + 10 * WSL, d_Wbl + 10 * WSL, p1_b, d_o, Nn);
    bn_stats_k<<<80, 256>>>(d_o);
    bn_final_k<<<1, 256>>>(pbn1_g, pbn1_b);
    bn_apply_k<<<Nn, HID>>>(d_o, d_h, 1);

    hgemm_k<<<grid1, 256>>>(d_Wbh + 11 * WSL, d_Wbl + 11 * WSL, p2_b, d_o,
                            d_Wbh + 11 * WSL, d_Wbl + 11 * WSL, p2_b, d_o, Nn);
    bn_stats_k<<<80, 256>>>(d_o);
    bn_final_k<<<1, 256>>>(pbn2_g, pbn2_b);
    bn_apply_k<<<Nn, HID>>>(d_o, d_h, 1);

    proj3_k<<<(Nn * 3 + 255) / 256, 256>>>(p3_W, p3_b, out);
}